// round 2
// baseline (speedup 1.0000x reference)
#include <cuda_runtime.h>
#include <math.h>
#include <stdint.h>

#define NTOT   131072
#define HH     256
#define H0V    64
#define W0V    64
#define CEMB   32
#define CPE    128
#define INDIM  202
#define NF4    512
#define NF2    256
#define NHEAD  129
#define NFEAT  128
#define FINEIN 330
#define KSEL   26214
#define INVF        0.9999950000374997f
#define TWO_PI_F    6.2831854820251465f
#define HALF_PI_F   1.5707963705062866f

// ---------------- scratch ----------------
__device__ float g_feat   [ (size_t)NTOT * INDIM ];
__device__ float g_x1     [ (size_t)NTOT * NF4   ];
__device__ float g_x2     [ (size_t)NTOT * NF2   ];
__device__ float g_head   [ (size_t)NTOT * NHEAD ];
__device__ float g_segfeat[ (size_t)NTOT * NFEAT ];
__device__ float g_segc   [ NTOT ];
__device__ float g_var    [ NTOT ];
__device__ float g_finein [ (size_t)KSEL * FINEIN ];
__device__ float g_y1     [ (size_t)KSEL * NFEAT ];
__device__ float g_y2     [ (size_t)KSEL * NFEAT ];
__device__ float g_z1     [ (size_t)KSEL * 64 ];
__device__ int   g_sel    [ KSEL ];
__device__ int   g_eq     [ 8192 ];
__device__ unsigned g_hist[3][2048];
__device__ unsigned g_cnt_gt, g_cnt_eq;
__device__ unsigned g_thresh_bits;
__device__ int      g_need_eq;
__device__ unsigned g_bin[3];
__device__ unsigned g_need_s;
__device__ int      g_maskmode;
__device__ float g_tab[256][20];
__device__ float g_coord[256];

// ---------------- mask dtype ----------------
// 0=bool bytes, 1=int32, 2=float32, 3=int64, 4=float64
__device__ __forceinline__ float maskval(const void* p, size_t idx, int mode) {
    switch (mode) {
        case 0: return ((const unsigned char*)p)[idx] ? 1.f : 0.f;
        case 1: return ((const int*)p)[idx] ? 1.f : 0.f;
        case 2: return ((const float*)p)[idx];
        case 3: return ((const long long*)p)[idx] ? 1.f : 0.f;
        default: return (float)((const double*)p)[idx];
    }
}

__global__ void k_detect(const unsigned* __restrict__ p) {
    if (threadIdx.x || blockIdx.x) return;
    bool f32 = false, f64 = false, gt1 = false, oddnz = false;
    for (int i = 0; i < 2048; i++) {
        unsigned v = p[i];
        if (v == 0x3F800000u) f32 = true;
        else if (v == 0x3FF00000u) { if (i & 1) f64 = true; else gt1 = true; }
        else if (v > 1u) gt1 = true;
        if ((i & 1) && v) oddnz = true;
    }
    int mode;
    if (f64) mode = 4;
    else if (f32) mode = 2;
    else if (gt1) mode = 0;
    else if (!oddnz) mode = 3;
    else mode = 1;
    g_maskmode = mode;
}

__global__ void k_reset() {
    int t = threadIdx.x;
    unsigned* h = &g_hist[0][0];
    for (int i = t; i < 3 * 2048; i += blockDim.x) h[i] = 0u;
    if (t == 0) { g_cnt_gt = 0u; g_cnt_eq = 0u; }
}

// ---------------- positional tables ----------------
__global__ void k_postab() {
    int t = threadIdx.x;  // 0..255
    if (t >= 256) return;
    const float step = 2.0f / 255.0f;          // rn(2/255)
    float c = __fadd_rn(-1.0f, __fmul_rn((float)t, step));
    g_coord[t] = c;
    float sc = __fmul_rn(TWO_PI_F, c);
    const float f109 = 10.0f / 9.0f;           // rn(10/9)
    for (int j = 0; j < 10; j++) {
        float xj = __fmul_rn((float)j, f109);
        float fr = (float)exp2((double)xj);    // correctly rounded
        float ph = __fmul_rn(sc, fr);
        g_tab[t][j]      = (float)sin((double)ph);
        float ph2 = __fadd_rn(ph, HALF_PI_F);
        g_tab[t][10 + j] = (float)sin((double)ph2);
    }
}

// ---------------- feat build ----------------
__global__ void k_feat(const float* __restrict__ emb, const float* __restrict__ pe) {
    size_t idx = (size_t)blockIdx.x * blockDim.x + threadIdx.x;
    if (idx >= (size_t)NTOT * INDIM) return;
    int c = (int)(idx % INDIM);
    int n = (int)(idx / INDIM);
    int b = n >> 16;
    int y = (n >> 8) & 255;
    int x = n & 255;
    float val;
    if (c < CEMB + CPE) {
        const float* plane;
        if (c < CEMB) plane = emb + ((size_t)b * CEMB + c) * (H0V * W0V);
        else          plane = pe  + ((size_t)b * CPE + (c - CEMB)) * (H0V * W0V);
        float cyf = ((float)y + 0.5f) * 0.25f - 0.5f;   // exact multiples of 1/8
        float cxf = ((float)x + 0.5f) * 0.25f - 0.5f;
        float fy0 = floorf(cyf), fx0 = floorf(cxf);
        float fy = cyf - fy0, fx = cxf - fx0;           // exact
        int y0 = (int)fy0, x0 = (int)fx0;
        int iy0 = min(max(y0, 0), H0V - 1), iy1 = min(max(y0 + 1, 0), H0V - 1);
        int ix0 = min(max(x0, 0), W0V - 1), ix1 = min(max(x0 + 1, 0), W0V - 1);
        float v00 = plane[iy0 * W0V + ix0], v01 = plane[iy0 * W0V + ix1];
        float v10 = plane[iy1 * W0V + ix0], v11 = plane[iy1 * W0V + ix1];
        float wy0 = 1.f - fy, wx0 = 1.f - fx;
        float t0, t1;
        if (iy0 == iy1) { t0 = v00; t1 = v01; }  // edge renorm -> exact copy
        else {
            t0 = __fadd_rn(__fmul_rn(v00, wy0), __fmul_rn(v10, fy));
            t1 = __fadd_rn(__fmul_rn(v01, wy0), __fmul_rn(v11, fy));
        }
        if (ix0 == ix1) val = t0;
        else val = __fadd_rn(__fmul_rn(t0, wx0), __fmul_rn(t1, fx));
    } else {
        int p = c - (CEMB + CPE);
        if      (p < 10) val = g_tab[y][p];
        else if (p < 20) val = g_tab[x][p - 10];
        else if (p < 30) val = g_tab[y][p - 10];
        else if (p < 40) val = g_tab[x][p - 20];
        else val = (p == 40) ? g_coord[y] : g_coord[x];
    }
    g_feat[idx] = val;
}

// ---------------- SGEMM: C[M,N] = A[M,K] @ B[K,N], epilogue ----------------
// EPI 0: C = acc + bias         EPI 1: C = relu((acc+bias)*rn(g*INVF)+be)
template<int EPI>
__global__ void __launch_bounds__(256, 2) k_gemm(
    const float* __restrict__ A, const float* __restrict__ B,
    const float* __restrict__ bias, const float* __restrict__ g,
    const float* __restrict__ be, float* __restrict__ C,
    int M, int K, int N)
{
    __shared__ float As[8][128];
    __shared__ float Bs[8][128];
    int bm = blockIdx.y * 128, bn = blockIdx.x * 128;
    int t = threadIdx.x;
    int tr = t >> 4, tc = t & 15;
    float acc[8][8];
    #pragma unroll
    for (int i = 0; i < 8; i++)
        #pragma unroll
        for (int j = 0; j < 8; j++) acc[i][j] = 0.f;

    for (int k0 = 0; k0 < K; k0 += 8) {
        #pragma unroll
        for (int i = 0; i < 4; i++) {
            int e = t * 4 + i;
            int m  = e >> 3, kk = e & 7;
            int gm = bm + m, gk = k0 + kk;
            As[kk][m] = (gm < M && gk < K) ? A[(size_t)gm * K + gk] : 0.f;
            int kb = e >> 7, nb = e & 127;
            int gkb = k0 + kb, gn = bn + nb;
            Bs[kb][nb] = (gkb < K && gn < N) ? B[(size_t)gkb * N + gn] : 0.f;
        }
        __syncthreads();
        #pragma unroll
        for (int kk = 0; kk < 8; kk++) {
            float a[8], bb[8];
            #pragma unroll
            for (int j = 0; j < 8; j++) a[j]  = As[kk][tr * 8 + j];
            #pragma unroll
            for (int j = 0; j < 8; j++) bb[j] = Bs[kk][tc * 8 + j];
            #pragma unroll
            for (int i = 0; i < 8; i++)
                #pragma unroll
                for (int j = 0; j < 8; j++) acc[i][j] = fmaf(a[i], bb[j], acc[i][j]);
        }
        __syncthreads();
    }
    #pragma unroll
    for (int i = 0; i < 8; i++) {
        int gm = bm + tr * 8 + i;
        if (gm >= M) continue;
        #pragma unroll
        for (int j = 0; j < 8; j++) {
            int gn = bn + tc * 8 + j;
            if (gn >= N) continue;
            float v = __fadd_rn(acc[i][j], bias[gn]);
            if (EPI == 1) {
                float s = __fmul_rn(g[gn], INVF);
                v = __fadd_rn(__fmul_rn(v, s), be[gn]);
                v = fmaxf(v, 0.f);
            }
            C[(size_t)gm * N + gn] = v;
        }
    }
}

// ---------------- head post: segc / segfeat / var ----------------
__global__ void k_post(const void* __restrict__ dm1, const void* __restrict__ dm2) {
    int w = (int)((blockIdx.x * (size_t)blockDim.x + threadIdx.x) >> 5);
    int lane = threadIdx.x & 31;
    if (w >= NTOT) return;
    int mode = g_maskmode;
    const float* hrow = g_head + (size_t)w * NHEAD;
    float acc = 0.f;
    for (int c = lane; c < NHEAD; c += 32) {
        float h = hrow[c];
        size_t mi = (size_t)w * NHEAD + c;
        float m1 = maskval(dm1, mi, mode);
        float m2 = maskval(dm2, mi, mode);
        float o2 = __fmul_rn(__fmul_rn(h, m2), 2.0f);
        if (c == 0) g_segc[w] = o2;
        else        g_segfeat[(size_t)w * NFEAT + (c - 1)] = o2;
        float o1 = __fmul_rn(__fmul_rn(h, m1), 2.0f);
        float d  = __fsub_rn(o1, o2);
        acc = __fadd_rn(acc, __fmul_rn(0.5f, __fmul_rn(d, d)));
    }
    #pragma unroll
    for (int o = 16; o; o >>= 1) acc = __fadd_rn(acc, __shfl_xor_sync(~0u, acc, o));
    if (!lane) g_var[w] = __fdiv_rn(acc, 129.0f);
}

// ---------------- top-k (exact threshold via 3-pass radix) ----------------
__global__ void k_hist(int phase) {
    int i = blockIdx.x * blockDim.x + threadIdx.x;
    if (i >= NTOT) return;
    unsigned key = __float_as_uint(g_var[i]);
    if (phase == 0) atomicAdd(&g_hist[0][key >> 21], 1u);
    else if (phase == 1) {
        if ((key >> 21) == g_bin[0]) atomicAdd(&g_hist[1][(key >> 10) & 0x7FFu], 1u);
    } else {
        if ((key >> 10) == ((g_bin[0] << 11) | g_bin[1]))
            atomicAdd(&g_hist[2][key & 0x3FFu], 1u);
    }
}

__global__ void k_scan(int phase) {
    if (threadIdx.x || blockIdx.x) return;
    unsigned need = (phase == 0) ? (unsigned)KSEL : g_need_s;
    unsigned acc = 0;
    int b;
    int top = (phase == 2) ? 1023 : 2047;
    for (b = top; b > 0; b--) {
        unsigned h = g_hist[phase][b];
        if (acc + h >= need) break;
        acc += h;
    }
    g_bin[phase] = (unsigned)b;
    g_need_s = need - acc;
    if (phase == 2) {
        g_thresh_bits = (g_bin[0] << 21) | (g_bin[1] << 10) | (unsigned)b;
        g_need_eq = (int)(need - acc);
    }
}

__global__ void k_compact() {
    int i = blockIdx.x * blockDim.x + threadIdx.x;
    if (i >= NTOT) return;
    unsigned key = __float_as_uint(g_var[i]);
    unsigned T = g_thresh_bits;
    if (key > T) {
        unsigned s = atomicAdd(&g_cnt_gt, 1u);
        g_sel[s] = i;
    } else if (key == T) {
        unsigned e = atomicAdd(&g_cnt_eq, 1u);
        if (e < 8192u) g_eq[e] = i;
    }
}

__global__ void k_eqsel() {
    int c = (int)g_cnt_eq; if (c > 8192) c = 8192;
    int need = g_need_eq;
    int G = KSEL - need;
    for (int i = threadIdx.x; i < c; i += blockDim.x) {
        int v = g_eq[i];
        int rank = 0;
        for (int j = 0; j < c; j++) rank += (g_eq[j] < v) ? 1 : 0;
        if (rank < need) g_sel[G + rank] = v;
    }
}

// ---------------- gather fine inputs ----------------
__global__ void k_gather() {
    size_t idx = (size_t)blockIdx.x * blockDim.x + threadIdx.x;
    if (idx >= (size_t)KSEL * FINEIN) return;
    int j = (int)(idx / FINEIN);
    int c = (int)(idx % FINEIN);
    int s = g_sel[j];
    float v = (c < INDIM) ? g_feat[(size_t)s * INDIM + c]
                          : g_segfeat[(size_t)s * NFEAT + (c - INDIM)];
    g_finein[idx] = v;
}

// ---------------- output assembly ----------------
__global__ void k_out(float* __restrict__ out) {
    int i = blockIdx.x * blockDim.x + threadIdx.x;
    if (i >= NTOT) return;
    float v = g_segc[i];
    out[i] = v;
    out[NTOT + i] = v;
}

__global__ void k_zdot(const float* __restrict__ w3b, const float* __restrict__ b3b,
                       float* __restrict__ out) {
    int j = (int)((blockIdx.x * (size_t)blockDim.x + threadIdx.x) >> 5);
    int lane = threadIdx.x & 31;
    if (j >= KSEL) return;
    const float* zr = g_z1 + (size_t)j * 64;
    float acc = __fadd_rn(__fmul_rn(zr[lane], w3b[lane]),
                          __fmul_rn(zr[32 + lane], w3b[32 + lane]));
    #pragma unroll
    for (int o = 16; o; o >>= 1) acc = __fadd_rn(acc, __shfl_xor_sync(~0u, acc, o));
    if (!lane) out[NTOT + g_sel[j]] = __fadd_rn(acc, b3b[0]);
}

// ---------------- launch ----------------
extern "C" void kernel_launch(void* const* d_in, const int* in_sizes, int n_in,
                              void* d_out, int out_size) {
    const float* emb = (const float*)d_in[0];
    const float* pe  = (const float*)d_in[1];
    const void*  dm1 = d_in[2];
    const void*  dm2 = d_in[3];
    const float* w0a = (const float*)d_in[4];
    const float* b0a = (const float*)d_in[5];
    const float* g0a = (const float*)d_in[6];
    const float* be0a= (const float*)d_in[7];
    const float* w0b = (const float*)d_in[8];
    const float* b0b = (const float*)d_in[9];
    const float* g0b = (const float*)d_in[10];
    const float* be0b= (const float*)d_in[11];
    const float* w2  = (const float*)d_in[12];
    const float* b2  = (const float*)d_in[13];
    const float* w1a = (const float*)d_in[14];
    const float* b1a = (const float*)d_in[15];
    const float* g1a = (const float*)d_in[16];
    const float* be1a= (const float*)d_in[17];
    const float* w1b = (const float*)d_in[18];
    const float* b1b = (const float*)d_in[19];
    const float* g1b = (const float*)d_in[20];
    const float* be1b= (const float*)d_in[21];
    const float* w3a = (const float*)d_in[22];
    const float* b3a = (const float*)d_in[23];
    const float* g3a = (const float*)d_in[24];
    const float* be3a= (const float*)d_in[25];
    const float* w3b = (const float*)d_in[26];
    const float* b3b = (const float*)d_in[27];
    float* out = (float*)d_out;

    float *p_feat, *p_x1, *p_x2, *p_head, *p_fin, *p_y1, *p_y2, *p_z1;
    cudaGetSymbolAddress((void**)&p_feat, g_feat);
    cudaGetSymbolAddress((void**)&p_x1,   g_x1);
    cudaGetSymbolAddress((void**)&p_x2,   g_x2);
    cudaGetSymbolAddress((void**)&p_head, g_head);
    cudaGetSymbolAddress((void**)&p_fin,  g_finein);
    cudaGetSymbolAddress((void**)&p_y1,   g_y1);
    cudaGetSymbolAddress((void**)&p_y2,   g_y2);
    cudaGetSymbolAddress((void**)&p_z1,   g_z1);

    k_detect<<<1, 1>>>((const unsigned*)dm1);
    k_reset<<<1, 256>>>();
    k_postab<<<1, 256>>>();

    {
        size_t tot = (size_t)NTOT * INDIM;
        k_feat<<<(unsigned)((tot + 255) / 256), 256>>>(emb, pe);
    }

    // coarse MLP
    k_gemm<1><<<dim3(NF4 / 128, NTOT / 128), 256>>>(p_feat, w0a, b0a, g0a, be0a, p_x1, NTOT, INDIM, NF4);
    k_gemm<1><<<dim3(NF2 / 128, NTOT / 128), 256>>>(p_x1, w0b, b0b, g0b, be0b, p_x2, NTOT, NF4, NF2);
    k_gemm<0><<<dim3((NHEAD + 127) / 128, NTOT / 128), 256>>>(p_x2, w2, b2, b2, b2, p_head, NTOT, NF2, NHEAD);

    k_post<<<NTOT / 8, 256>>>(dm1, dm2);

    // top-k
    int hb = (NTOT + 255) / 256;
    k_hist<<<hb, 256>>>(0);
    k_scan<<<1, 1>>>(0);
    k_hist<<<hb, 256>>>(1);
    k_scan<<<1, 1>>>(1);
    k_hist<<<hb, 256>>>(2);
    k_scan<<<1, 1>>>(2);
    k_compact<<<hb, 256>>>();
    k_eqsel<<<1, 256>>>();

    {
        size_t tot = (size_t)KSEL * FINEIN;
        k_gather<<<(unsigned)((tot + 255) / 256), 256>>>();
    }

    // fine MLP
    int gy = (KSEL + 127) / 128;
    k_gemm<1><<<dim3(1, gy), 256>>>(p_fin, w1a, b1a, g1a, be1a, p_y1, KSEL, FINEIN, NFEAT);
    k_gemm<1><<<dim3(1, gy), 256>>>(p_y1, w1b, b1b, g1b, be1b, p_y2, KSEL, NFEAT, NFEAT);
    k_gemm<1><<<dim3(1, gy), 256>>>(p_y2, w3a, b3a, g3a, be3a, p_z1, KSEL, NFEAT, 64);

    k_out<<<NTOT / 256, 256>>>(out);
    k_zdot<<<(KSEL * 32 + 255) / 256, 256>>>(w3b, b3b, out);
}

// round 3
// speedup vs baseline: 1.6924x; 1.6924x over previous
#include <cuda_runtime.h>
#include <math.h>
#include <stdint.h>

#define NTOT   131072
#define H0V    64
#define W0V    64
#define CEMB   32
#define CPE    128
#define INDIM  202
#define KP0    208
#define NF4    512
#define NF2    256
#define NHEAD  129
#define NFEAT  128
#define FINEIN 330
#define KPF    336
#define KSEL   26214
#define MT     26368
#define INVF        0.9999950000374997f
#define TWO_PI_F    6.2831854820251465f
#define HALF_PI_F   1.5707963705062866f

// ---------------- scratch ----------------
__device__ float g_featT  [ (size_t)KP0 * NTOT ];
__device__ float g_x1T    [ (size_t)NF4 * NTOT ];
__device__ float g_x2T    [ (size_t)NF2 * NTOT ];
__device__ float g_head   [ (size_t)NTOT * NFEAT ];   // cols 0..127 of head, row-major
__device__ float g_hcol   [ NTOT ];                   // head col 128
__device__ float g_segfeat[ (size_t)NTOT * NFEAT ];
__device__ float g_segc   [ NTOT ];
__device__ float g_var    [ NTOT ];
__device__ float g_fineinT[ (size_t)KPF * MT ];
__device__ float g_y1T    [ (size_t)NFEAT * MT ];
__device__ float g_y2T    [ (size_t)NFEAT * MT ];
__device__ float g_zT     [ (size_t)64 * MT ];
__device__ float g_w2p    [ 256 * 128 ];
__device__ float g_w2c    [ 256 ];
__device__ int   g_sel    [ KSEL ];
__device__ int   g_eq     [ 8192 ];
__device__ unsigned g_hist[3][2048];
__device__ unsigned g_cnt_gt, g_cnt_eq;
__device__ unsigned g_thresh_bits;
__device__ int      g_need_eq;
__device__ unsigned g_bin[3];
__device__ unsigned g_need_s;
__device__ int      g_maskmode;
__device__ float g_tab[256][20];
__device__ float g_coord[256];

// ---------------- mask dtype ----------------
__device__ __forceinline__ float maskval(const void* p, size_t idx, int mode) {
    switch (mode) {
        case 0: return ((const unsigned char*)p)[idx] ? 1.f : 0.f;
        case 1: return ((const int*)p)[idx] ? 1.f : 0.f;
        case 2: return ((const float*)p)[idx];
        case 3: return ((const long long*)p)[idx] ? 1.f : 0.f;
        default: return (float)((const double*)p)[idx];
    }
}

__global__ void k_detect(const unsigned* __restrict__ p) {
    if (threadIdx.x || blockIdx.x) return;
    bool f32 = false, f64 = false, gt1 = false, oddnz = false;
    for (int i = 0; i < 2048; i++) {
        unsigned v = p[i];
        if (v == 0x3F800000u) f32 = true;
        else if (v == 0x3FF00000u) { if (i & 1) f64 = true; else gt1 = true; }
        else if (v > 1u) gt1 = true;
        if ((i & 1) && v) oddnz = true;
    }
    int mode;
    if (f64) mode = 4;
    else if (f32) mode = 2;
    else if (gt1) mode = 0;
    else if (!oddnz) mode = 3;
    else mode = 1;
    g_maskmode = mode;
}

__global__ void k_reset() {
    int t = threadIdx.x;
    unsigned* h = &g_hist[0][0];
    for (int i = t; i < 3 * 2048; i += blockDim.x) h[i] = 0u;
    if (t == 0) { g_cnt_gt = 0u; g_cnt_eq = 0u; }
}

// ---------------- positional tables ----------------
__global__ void k_postab() {
    int t = threadIdx.x;
    if (t >= 256) return;
    const float step = 2.0f / 255.0f;
    float c = __fadd_rn(-1.0f, __fmul_rn((float)t, step));
    g_coord[t] = c;
    float sc = __fmul_rn(TWO_PI_F, c);
    const float f109 = 10.0f / 9.0f;
    for (int j = 0; j < 10; j++) {
        float xj = __fmul_rn((float)j, f109);
        float fr = (float)exp2((double)xj);
        float ph = __fmul_rn(sc, fr);
        g_tab[t][j]      = (float)sin((double)ph);
        float ph2 = __fadd_rn(ph, HALF_PI_F);
        g_tab[t][10 + j] = (float)sin((double)ph2);
    }
}

// ---------------- feat build (transposed layout: featT[c][n]) ----------------
__global__ void k_feat(const float* __restrict__ emb, const float* __restrict__ pe) {
    size_t idx = (size_t)blockIdx.x * 256 + threadIdx.x;   // < KP0*NTOT
    int c = (int)(idx >> 17);
    int n = (int)(idx & (NTOT - 1));
    int b = n >> 16;
    int y = (n >> 8) & 255;
    int x = n & 255;
    float val;
    if (c >= INDIM) {
        val = 0.f;
    } else if (c < CEMB + CPE) {
        const float* plane;
        if (c < CEMB) plane = emb + ((size_t)b * CEMB + c) * (H0V * W0V);
        else          plane = pe  + ((size_t)b * CPE + (c - CEMB)) * (H0V * W0V);
        float cyf = ((float)y + 0.5f) * 0.25f - 0.5f;
        float cxf = ((float)x + 0.5f) * 0.25f - 0.5f;
        float fy0 = floorf(cyf), fx0 = floorf(cxf);
        float fy = cyf - fy0, fx = cxf - fx0;
        int y0 = (int)fy0, x0 = (int)fx0;
        int iy0 = min(max(y0, 0), H0V - 1), iy1 = min(max(y0 + 1, 0), H0V - 1);
        int ix0 = min(max(x0, 0), W0V - 1), ix1 = min(max(x0 + 1, 0), W0V - 1);
        float v00 = plane[iy0 * W0V + ix0], v01 = plane[iy0 * W0V + ix1];
        float v10 = plane[iy1 * W0V + ix0], v11 = plane[iy1 * W0V + ix1];
        float wy0 = 1.f - fy, wx0 = 1.f - fx;
        float t0, t1;
        if (iy0 == iy1) { t0 = v00; t1 = v01; }
        else {
            t0 = __fadd_rn(__fmul_rn(v00, wy0), __fmul_rn(v10, fy));
            t1 = __fadd_rn(__fmul_rn(v01, wy0), __fmul_rn(v11, fy));
        }
        if (ix0 == ix1) val = t0;
        else val = __fadd_rn(__fmul_rn(t0, wx0), __fmul_rn(t1, fx));
    } else {
        int p = c - (CEMB + CPE);
        if      (p < 10) val = g_tab[y][p];
        else if (p < 20) val = g_tab[x][p - 10];
        else if (p < 30) val = g_tab[y][p - 10];
        else if (p < 40) val = g_tab[x][p - 20];
        else val = (p == 40) ? g_coord[y] : g_coord[x];
    }
    g_featT[idx] = val;
}

// ---------------- FFMA2 SGEMM ----------------
// C[M,N] = A[M,K] @ B[K,N]; A given TRANSPOSED At[Kpad][ldA].
// BM=256, BN=128, BK=16, 256 threads, 16x8 per thread via packed f32x2.
// Per-output accumulation: single chain, strictly k-ascending -> bit-identical
// to the previous scalar kernel.
#define FFMA2(d,a,b) asm("fma.rn.f32x2 %0, %1, %2, %0;" : "+l"(d) : "l"(a), "l"(b))

template<int EPI, int TRANSC>
__global__ void __launch_bounds__(256, 1) k_gemm2(
    const float* __restrict__ At, const float* __restrict__ B,
    const float* __restrict__ bias, const float* __restrict__ g,
    const float* __restrict__ be, float* __restrict__ C,
    int M, int Kpad, int Klog, int N, int ldA, int ldB, int ldC)
{
    extern __shared__ float sm[];
    float* As = sm;            // 2 buffers x 16x256
    float* Bd = sm + 8192;     // 2 buffers x 16x(128 dup) quarter-interleaved
    const int t = threadIdx.x;
    const int bm = blockIdx.y * 256, bn = blockIdx.x * 128;
    const int tr = t >> 4, tc = t & 15;

    const float4* At4 = (const float4*)At;
    const float4* B4  = (const float4*)B;
    const int lda4 = ldA >> 2, ldb4 = ldB >> 2;

    float4 ra[4], rb[2];
    unsigned long long acc[8][8];
    #pragma unroll
    for (int i = 0; i < 8; i++)
        #pragma unroll
        for (int j = 0; j < 8; j++) acc[i][j] = 0ull;

    auto LOADG = [&](int k0) {
        #pragma unroll
        for (int i = 0; i < 4; i++) {
            int f = t + 256 * i;
            int kk = f >> 6, m4 = f & 63;
            ra[i] = At4[(size_t)(k0 + kk) * lda4 + (bm >> 2) + m4];
        }
        #pragma unroll
        for (int i = 0; i < 2; i++) {
            int f = t + 256 * i;
            int kk = f >> 5, c4 = f & 31;
            int gk = k0 + kk, gn = bn + c4 * 4;
            if (gk < Klog && gn < N) rb[i] = B4[(size_t)gk * ldb4 + (gn >> 2)];
            else rb[i] = make_float4(0.f, 0.f, 0.f, 0.f);
        }
    };
    auto STORES = [&](int buf) {
        float* Asb = As + buf * 4096;
        float* Bdb = Bd + buf * 4096;
        #pragma unroll
        for (int i = 0; i < 4; i++) {
            int f = t + 256 * i;
            int kk = f >> 6, m4 = f & 63;
            *(float4*)&Asb[kk * 256 + m4 * 4] = ra[i];
        }
        #pragma unroll
        for (int i = 0; i < 2; i++) {
            int f = t + 256 * i;
            int kk = f >> 5, c4 = f & 31;
            int tcb = c4 >> 1, qb = (c4 & 1) * 2;
            *(float4*)&Bdb[((kk * 4 + qb) * 16 + tcb) * 4] =
                make_float4(rb[i].x, rb[i].x, rb[i].y, rb[i].y);
            *(float4*)&Bdb[((kk * 4 + qb + 1) * 16 + tcb) * 4] =
                make_float4(rb[i].z, rb[i].z, rb[i].w, rb[i].w);
        }
    };
    auto COMPUTE = [&](int buf) {
        const float* Asb = As + buf * 4096;
        const float* Bdb = Bd + buf * 4096;
        #pragma unroll
        for (int kk = 0; kk < 16; kk++) {
            unsigned long long a2[8], b2[8];
            #pragma unroll
            for (int r = 0; r < 4; r++) {
                ulonglong2 v = *(const ulonglong2*)&Asb[kk * 256 + tr * 16 + r * 4];
                a2[2 * r] = v.x; a2[2 * r + 1] = v.y;
            }
            #pragma unroll
            for (int q = 0; q < 4; q++) {
                ulonglong2 v = *(const ulonglong2*)&Bdb[(kk * 4 + q) * 64 + tc * 4];
                b2[2 * q] = v.x; b2[2 * q + 1] = v.y;
            }
            #pragma unroll
            for (int ip = 0; ip < 8; ip++)
                #pragma unroll
                for (int j = 0; j < 8; j++)
                    FFMA2(acc[ip][j], a2[ip], b2[j]);
        }
    };

    LOADG(0); STORES(0); __syncthreads();
    int nk = Kpad >> 4;
    int buf = 0;
    for (int it = 1; it < nk; it++) {
        LOADG(it * 16);
        COMPUTE(buf);
        STORES(buf ^ 1);
        __syncthreads();
        buf ^= 1;
    }
    COMPUTE(buf);

    // epilogue (identical op order to previous kernel)
    if (TRANSC) {
        #pragma unroll
        for (int j = 0; j < 8; j++) {
            int gn = bn + tc * 8 + j;
            if (gn >= N) continue;
            float bsv = bias[gn];
            float sv = 0.f, bev = 0.f;
            if (EPI == 1) { sv = __fmul_rn(g[gn], INVF); bev = be[gn]; }
            float v[16];
            #pragma unroll
            for (int ip = 0; ip < 8; ip++) {
                v[2 * ip]     = __uint_as_float((unsigned)(acc[ip][j] & 0xFFFFFFFFull));
                v[2 * ip + 1] = __uint_as_float((unsigned)(acc[ip][j] >> 32));
            }
            #pragma unroll
            for (int r = 0; r < 16; r++) {
                float x = __fadd_rn(v[r], bsv);
                if (EPI == 1) { x = __fadd_rn(__fmul_rn(x, sv), bev); x = fmaxf(x, 0.f); }
                v[r] = x;
            }
            int gmb = bm + tr * 16;
            if (gmb + 16 <= M) {
                #pragma unroll
                for (int r4 = 0; r4 < 4; r4++)
                    *(float4*)&C[(size_t)gn * ldC + gmb + r4 * 4] =
                        make_float4(v[r4 * 4], v[r4 * 4 + 1], v[r4 * 4 + 2], v[r4 * 4 + 3]);
            } else {
                for (int r = 0; r < 16; r++)
                    if (gmb + r < M) C[(size_t)gn * ldC + gmb + r] = v[r];
            }
        }
    } else {
        #pragma unroll
        for (int ip = 0; ip < 8; ip++) {
            #pragma unroll
            for (int h = 0; h < 2; h++) {
                int gm = bm + tr * 16 + 2 * ip + h;
                if (gm >= M) continue;
                float v[8];
                #pragma unroll
                for (int j = 0; j < 8; j++) {
                    unsigned long long a = acc[ip][j];
                    float x = h ? __uint_as_float((unsigned)(a >> 32))
                                : __uint_as_float((unsigned)(a & 0xFFFFFFFFull));
                    int gn = bn + tc * 8 + j;
                    x = __fadd_rn(x, bias[gn]);
                    if (EPI == 1) {
                        x = __fadd_rn(__fmul_rn(x, __fmul_rn(g[gn], INVF)), be[gn]);
                        x = fmaxf(x, 0.f);
                    }
                    v[j] = x;
                }
                int gn0 = bn + tc * 8;
                if (gn0 + 8 <= N) {
                    *(float4*)&C[(size_t)gm * ldC + gn0]     = make_float4(v[0], v[1], v[2], v[3]);
                    *(float4*)&C[(size_t)gm * ldC + gn0 + 4] = make_float4(v[4], v[5], v[6], v[7]);
                } else {
                    for (int j = 0; j < 8; j++)
                        if (gn0 + j < N) C[(size_t)gm * ldC + gn0 + j] = v[j];
                }
            }
        }
    }
}

// ---------------- w2 pack: [256][129] -> [256][128] + col vector ----------------
__global__ void k_packw2(const float* __restrict__ w2) {
    int i = blockIdx.x * 256 + threadIdx.x;
    if (i >= 256 * 129) return;
    int k = i / 129, j = i - k * 129;
    float v = w2[i];
    if (j < 128) g_w2p[k * 128 + j] = v;
    else g_w2c[k] = v;
}

// ---------------- head col 128 (bit-identical fmaf chain) ----------------
__global__ void k_hcol(const float* __restrict__ b2) {
    int n = blockIdx.x * 256 + threadIdx.x;
    float acc = 0.f;
    #pragma unroll 8
    for (int k = 0; k < 256; k++)
        acc = fmaf(g_x2T[(size_t)k * NTOT + n], g_w2c[k], acc);
    g_hcol[n] = __fadd_rn(acc, b2[128]);
}

// ---------------- head post: segc / segfeat / var (identical numerics) ----------
__global__ void k_post(const void* __restrict__ dm1, const void* __restrict__ dm2) {
    int w = (int)((blockIdx.x * (size_t)blockDim.x + threadIdx.x) >> 5);
    int lane = threadIdx.x & 31;
    if (w >= NTOT) return;
    int mode = g_maskmode;
    float acc = 0.f;
    for (int c = lane; c < NHEAD; c += 32) {
        float h = (c < 128) ? g_head[(size_t)w * 128 + c] : g_hcol[w];
        size_t mi = (size_t)w * NHEAD + c;
        float m1 = maskval(dm1, mi, mode);
        float m2 = maskval(dm2, mi, mode);
        float o2 = __fmul_rn(__fmul_rn(h, m2), 2.0f);
        if (c == 0) g_segc[w] = o2;
        else        g_segfeat[(size_t)w * NFEAT + (c - 1)] = o2;
        float o1 = __fmul_rn(__fmul_rn(h, m1), 2.0f);
        float d  = __fsub_rn(o1, o2);
        acc = __fadd_rn(acc, __fmul_rn(0.5f, __fmul_rn(d, d)));
    }
    #pragma unroll
    for (int o = 16; o; o >>= 1) acc = __fadd_rn(acc, __shfl_xor_sync(~0u, acc, o));
    if (!lane) g_var[w] = __fdiv_rn(acc, 129.0f);
}

// ---------------- top-k ----------------
__global__ void k_hist(int phase) {
    int i = blockIdx.x * blockDim.x + threadIdx.x;
    if (i >= NTOT) return;
    unsigned key = __float_as_uint(g_var[i]);
    if (phase == 0) atomicAdd(&g_hist[0][key >> 21], 1u);
    else if (phase == 1) {
        if ((key >> 21) == g_bin[0]) atomicAdd(&g_hist[1][(key >> 10) & 0x7FFu], 1u);
    } else {
        if ((key >> 10) == ((g_bin[0] << 11) | g_bin[1]))
            atomicAdd(&g_hist[2][key & 0x3FFu], 1u);
    }
}

__global__ void k_scan(int phase) {
    if (threadIdx.x || blockIdx.x) return;
    unsigned need = (phase == 0) ? (unsigned)KSEL : g_need_s;
    unsigned acc = 0;
    int b;
    int top = (phase == 2) ? 1023 : 2047;
    for (b = top; b > 0; b--) {
        unsigned h = g_hist[phase][b];
        if (acc + h >= need) break;
        acc += h;
    }
    g_bin[phase] = (unsigned)b;
    g_need_s = need - acc;
    if (phase == 2) {
        g_thresh_bits = (g_bin[0] << 21) | (g_bin[1] << 10) | (unsigned)b;
        g_need_eq = (int)(need - acc);
    }
}

__global__ void k_compact() {
    int i = blockIdx.x * blockDim.x + threadIdx.x;
    if (i >= NTOT) return;
    unsigned key = __float_as_uint(g_var[i]);
    unsigned T = g_thresh_bits;
    if (key > T) {
        unsigned s = atomicAdd(&g_cnt_gt, 1u);
        g_sel[s] = i;
    } else if (key == T) {
        unsigned e = atomicAdd(&g_cnt_eq, 1u);
        if (e < 8192u) g_eq[e] = i;
    }
}

__global__ void k_eqsel() {
    int c = (int)g_cnt_eq; if (c > 8192) c = 8192;
    int need = g_need_eq;
    int G = KSEL - need;
    for (int i = threadIdx.x; i < c; i += blockDim.x) {
        int v = g_eq[i];
        int rank = 0;
        for (int j = 0; j < c; j++) rank += (g_eq[j] < v) ? 1 : 0;
        if (rank < need) g_sel[G + rank] = v;
    }
}

// ---------------- gather (writes transposed fineinT[c][j]) ----------------
__global__ void k_gather() {
    size_t idx = (size_t)blockIdx.x * 256 + threadIdx.x;
    if (idx >= (size_t)KPF * KSEL) return;
    int c = (int)(idx / KSEL);
    int j = (int)(idx - (size_t)c * KSEL);
    int s = g_sel[j];
    float v;
    if (c < INDIM)       v = g_featT[(size_t)c * NTOT + s];
    else if (c < FINEIN) v = g_segfeat[(size_t)s * NFEAT + (c - INDIM)];
    else                 v = 0.f;
    g_fineinT[(size_t)c * MT + j] = v;
}

// ---------------- output ----------------
__global__ void k_out(float* __restrict__ out) {
    int i = blockIdx.x * blockDim.x + threadIdx.x;
    if (i >= NTOT) return;
    float v = g_segc[i];
    out[i] = v;
    out[NTOT + i] = v;
}

__global__ void k_zdot(const float* __restrict__ w3b, const float* __restrict__ b3b,
                       float* __restrict__ out) {
    int j = (int)((blockIdx.x * (size_t)blockDim.x + threadIdx.x) >> 5);
    int lane = threadIdx.x & 31;
    if (j >= KSEL) return;
    float v0  = g_zT[(size_t)lane * MT + j];
    float v32 = g_zT[(size_t)(32 + lane) * MT + j];
    float acc = __fadd_rn(__fmul_rn(v0, w3b[lane]), __fmul_rn(v32, w3b[32 + lane]));
    #pragma unroll
    for (int o = 16; o; o >>= 1) acc = __fadd_rn(acc, __shfl_xor_sync(~0u, acc, o));
    if (!lane) out[NTOT + g_sel[j]] = __fadd_rn(acc, b3b[0]);
}

// ---------------- launch ----------------
extern "C" void kernel_launch(void* const* d_in, const int* in_sizes, int n_in,
                              void* d_out, int out_size) {
    const float* emb = (const float*)d_in[0];
    const float* pe  = (const float*)d_in[1];
    const void*  dm1 = d_in[2];
    const void*  dm2 = d_in[3];
    const float* w0a = (const float*)d_in[4];
    const float* b0a = (const float*)d_in[5];
    const float* g0a = (const float*)d_in[6];
    const float* be0a= (const float*)d_in[7];
    const float* w0b = (const float*)d_in[8];
    const float* b0b = (const float*)d_in[9];
    const float* g0b = (const float*)d_in[10];
    const float* be0b= (const float*)d_in[11];
    const float* w2  = (const float*)d_in[12];
    const float* b2  = (const float*)d_in[13];
    const float* w1a = (const float*)d_in[14];
    const float* b1a = (const float*)d_in[15];
    const float* g1a = (const float*)d_in[16];
    const float* be1a= (const float*)d_in[17];
    const float* w1b = (const float*)d_in[18];
    const float* b1b = (const float*)d_in[19];
    const float* g1b = (const float*)d_in[20];
    const float* be1b= (const float*)d_in[21];
    const float* w3a = (const float*)d_in[22];
    const float* b3a = (const float*)d_in[23];
    const float* g3a = (const float*)d_in[24];
    const float* be3a= (const float*)d_in[25];
    const float* w3b = (const float*)d_in[26];
    const float* b3b = (const float*)d_in[27];
    float* out = (float*)d_out;

    const int SMEMSZ = 65536;
    cudaFuncSetAttribute(k_gemm2<1,1>, cudaFuncAttributeMaxDynamicSharedMemorySize, SMEMSZ);
    cudaFuncSetAttribute(k_gemm2<0,0>, cudaFuncAttributeMaxDynamicSharedMemorySize, SMEMSZ);

    float *p_featT, *p_x1T, *p_x2T, *p_head, *p_fin, *p_y1T, *p_y2T, *p_zT, *p_w2p;
    cudaGetSymbolAddress((void**)&p_featT, g_featT);
    cudaGetSymbolAddress((void**)&p_x1T,   g_x1T);
    cudaGetSymbolAddress((void**)&p_x2T,   g_x2T);
    cudaGetSymbolAddress((void**)&p_head,  g_head);
    cudaGetSymbolAddress((void**)&p_fin,   g_fineinT);
    cudaGetSymbolAddress((void**)&p_y1T,   g_y1T);
    cudaGetSymbolAddress((void**)&p_y2T,   g_y2T);
    cudaGetSymbolAddress((void**)&p_zT,    g_zT);
    cudaGetSymbolAddress((void**)&p_w2p,   g_w2p);

    k_detect<<<1, 1>>>((const unsigned*)dm1);
    k_reset<<<1, 256>>>();
    k_postab<<<1, 256>>>();
    k_packw2<<<(256 * 129 + 255) / 256, 256>>>(w2);

    {
        size_t tot = (size_t)KP0 * NTOT;
        k_feat<<<(unsigned)(tot / 256), 256>>>(emb, pe);
    }

    // coarse MLP
    k_gemm2<1,1><<<dim3(NF4/128, NTOT/256), 256, SMEMSZ>>>(p_featT, w0a, b0a, g0a, be0a, p_x1T, NTOT, KP0, INDIM, NF4, NTOT, NF4, NTOT);
    k_gemm2<1,1><<<dim3(NF2/128, NTOT/256), 256, SMEMSZ>>>(p_x1T, w0b, b0b, g0b, be0b, p_x2T, NTOT, NF4, NF4, NF2, NTOT, NF2, NTOT);
    k_gemm2<0,0><<<dim3(1, NTOT/256), 256, SMEMSZ>>>(p_x2T, p_w2p, b2, b2, b2, p_head, NTOT, NF2, NF2, 128, NTOT, 128, 128);
    k_hcol<<<NTOT/256, 256>>>(b2);

    k_post<<<NTOT/8, 256>>>(dm1, dm2);

    // top-k
    int hb = (NTOT + 255) / 256;
    k_hist<<<hb, 256>>>(0);
    k_scan<<<1, 1>>>(0);
    k_hist<<<hb, 256>>>(1);
    k_scan<<<1, 1>>>(1);
    k_hist<<<hb, 256>>>(2);
    k_scan<<<1, 1>>>(2);
    k_compact<<<hb, 256>>>();
    k_eqsel<<<1, 256>>>();

    {
        size_t tot = (size_t)KPF * KSEL;
        k_gather<<<(unsigned)((tot + 255) / 256), 256>>>();
    }

    // fine MLP
    int gy = (KSEL + 255) / 256;   // 103 -> covers MT=26368
    k_gemm2<1,1><<<dim3(1, gy), 256, SMEMSZ>>>(p_fin, w1a, b1a, g1a, be1a, p_y1T, KSEL, KPF, FINEIN, NFEAT, MT, NFEAT, MT);
    k_gemm2<1,1><<<dim3(1, gy), 256, SMEMSZ>>>(p_y1T, w1b, b1b, g1b, be1b, p_y2T, KSEL, NFEAT, NFEAT, NFEAT, MT, NFEAT, MT);
    k_gemm2<1,1><<<dim3(1, gy), 256, SMEMSZ>>>(p_y2T, w3a, b3a, g3a, be3a, p_zT, KSEL, NFEAT, NFEAT, 64, MT, 64, MT);

    k_out<<<NTOT/256, 256>>>(out);
    k_zdot<<<(KSEL * 32 + 255) / 256, 256>>>(w3b, b3b, out);
}

// round 4
// speedup vs baseline: 2.5230x; 1.4908x over previous
#include <cuda_runtime.h>
#include <math.h>
#include <stdint.h>

#define NTOT   131072
#define H0V    64
#define W0V    64
#define CEMB   32
#define CPE    128
#define INDIM  202
#define NF4    512
#define NF2    256
#define NHEAD  129
#define NFEAT  128
#define FINEIN 330
#define KPF    336
#define KSEL   26214
#define MT     26368
#define NLOW   8192
#define INVF        0.9999950000374997f
#define TWO_PI_F    6.2831854820251465f
#define HALF_PI_F   1.5707963705062866f

// ---------------- scratch ----------------
__device__ float g_lowT   [ (size_t)160 * NLOW ];     // low-res feat, transposed
__device__ float g_embw   [ (size_t)NLOW * NF4 ];     // low-res feat @ w0a[0:160], row-major
__device__ float g_posy   [ 256 * NF4 ];
__device__ float g_posx   [ 256 * NF4 ];
__device__ float g_x1T    [ (size_t)NF4 * NTOT ];
__device__ float g_x2T    [ (size_t)NF2 * NTOT ];
__device__ float g_head   [ (size_t)NTOT * NFEAT ];   // head cols 0..127
__device__ float g_hcol   [ NTOT ];                   // head col 128
__device__ float g_segc   [ NTOT ];
__device__ float g_var    [ NTOT ];
__device__ float g_fineinT[ (size_t)KPF * MT ];
__device__ float g_y1T    [ (size_t)NFEAT * MT ];
__device__ float g_y2T    [ (size_t)NFEAT * MT ];
__device__ float g_zT     [ (size_t)64 * MT ];
__device__ float g_w2p    [ 256 * 128 ];
__device__ float g_w2c    [ 256 ];
__device__ int   g_sel    [ KSEL ];
__device__ int   g_eq     [ 8192 ];
__device__ unsigned g_hist[3][2048];
__device__ unsigned g_cnt_gt, g_cnt_eq;
__device__ unsigned g_thresh_bits;
__device__ int      g_need_eq;
__device__ unsigned g_bin[3];
__device__ unsigned g_need_s;
__device__ int      g_maskmode;
__device__ float g_tab[256][20];
__device__ float g_coord[256];

// ---------------- mask dtype ----------------
__device__ __forceinline__ float maskval(const void* p, size_t idx, int mode) {
    switch (mode) {
        case 0: return ((const unsigned char*)p)[idx] ? 1.f : 0.f;
        case 1: return ((const int*)p)[idx] ? 1.f : 0.f;
        case 2: return ((const float*)p)[idx];
        case 3: return ((const long long*)p)[idx] ? 1.f : 0.f;
        default: return (float)((const double*)p)[idx];
    }
}

// ---------------- merged prelude ----------------
// block 0: mask dtype detect; block 1: hist/counter reset; block 2: pos tables;
// blocks 3..131: w2 pack.
__global__ void k_prelude(const unsigned* __restrict__ dm, const float* __restrict__ w2) {
    int bid = blockIdx.x, t = threadIdx.x;
    if (bid == 0) {
        __shared__ int sf[4];
        if (t < 4) sf[t] = 0;
        __syncthreads();
        bool f32 = false, f64 = false, gt1 = false, oddnz = false;
        for (int i = t; i < 2048; i += 256) {
            unsigned v = dm[i];
            if (v == 0x3F800000u) f32 = true;
            else if (v == 0x3FF00000u) { if (i & 1) f64 = true; else gt1 = true; }
            else if (v > 1u) gt1 = true;
            if ((i & 1) && v) oddnz = true;
        }
        if (f32)  atomicOr(&sf[0], 1);
        if (f64)  atomicOr(&sf[1], 1);
        if (gt1)  atomicOr(&sf[2], 1);
        if (oddnz) atomicOr(&sf[3], 1);
        __syncthreads();
        if (t == 0) {
            int mode;
            if (sf[1]) mode = 4;
            else if (sf[0]) mode = 2;
            else if (sf[2]) mode = 0;
            else if (!sf[3]) mode = 3;
            else mode = 1;
            g_maskmode = mode;
        }
    } else if (bid == 1) {
        unsigned* h = &g_hist[0][0];
        for (int i = t; i < 3 * 2048; i += 256) h[i] = 0u;
        if (t == 0) { g_cnt_gt = 0u; g_cnt_eq = 0u; }
    } else if (bid == 2) {
        const float step = 2.0f / 255.0f;
        float c = __fadd_rn(-1.0f, __fmul_rn((float)t, step));
        g_coord[t] = c;
        float sc = __fmul_rn(TWO_PI_F, c);
        const float f109 = 10.0f / 9.0f;
        for (int j = 0; j < 10; j++) {
            float xj = __fmul_rn((float)j, f109);
            float fr = (float)exp2((double)xj);
            float ph = __fmul_rn(sc, fr);
            g_tab[t][j]      = (float)sin((double)ph);
            float ph2 = __fadd_rn(ph, HALF_PI_F);
            g_tab[t][10 + j] = (float)sin((double)ph2);
        }
    } else {
        int i = (bid - 3) * 256 + t;
        if (i < 256 * 129) {
            int k = i / 129, j = i - k * 129;
            float v = w2[i];
            if (j < 128) g_w2p[k * 128 + j] = v;
            else g_w2c[k] = v;
        }
    }
}

// ---------------- low-res feat (transposed): lowT[c][m] ----------------
__global__ void k_lowT(const float* __restrict__ emb, const float* __restrict__ pe) {
    int idx = blockIdx.x * 256 + threadIdx.x;
    if (idx >= 160 * NLOW) return;
    int c = idx >> 13;
    int m = idx & (NLOW - 1);
    int b = m >> 12, p = m & 4095;
    float v = (c < CEMB) ? emb[((size_t)(b * CEMB + c)) * 4096 + p]
                         : pe [((size_t)(b * CPE + (c - CEMB))) * 4096 + p];
    g_lowT[idx] = v;
}

// ---------------- pos weight tables ----------------
__global__ void k_posw(const float* __restrict__ w0a) {
    int idx = blockIdx.x * 256 + threadIdx.x;
    if (idx >= 256 * NF4) return;
    int v = idx >> 9, j = idx & 511;
    float ay = 0.f, ax = 0.f;
    #pragma unroll
    for (int t = 0; t < 10; t++) ay = fmaf(g_tab[v][t],      w0a[(160 + t) * NF4 + j], ay);
    #pragma unroll
    for (int t = 0; t < 10; t++) ay = fmaf(g_tab[v][10 + t], w0a[(180 + t) * NF4 + j], ay);
    ay = fmaf(g_coord[v], w0a[200 * NF4 + j], ay);
    #pragma unroll
    for (int t = 0; t < 10; t++) ax = fmaf(g_tab[v][t],      w0a[(170 + t) * NF4 + j], ax);
    #pragma unroll
    for (int t = 0; t < 10; t++) ax = fmaf(g_tab[v][10 + t], w0a[(190 + t) * NF4 + j], ax);
    ax = fmaf(g_coord[v], w0a[201 * NF4 + j], ax);
    g_posy[idx] = ay;
    g_posx[idx] = ax;
}

// ---------------- FFMA2 SGEMM (EPI 0: +bias; 1: relu(bn(+bias)); 2: raw) ------
#define FFMA2(d,a,b) asm("fma.rn.f32x2 %0, %1, %2, %0;" : "+l"(d) : "l"(a), "l"(b))

template<int EPI, int TRANSC>
__global__ void __launch_bounds__(256, 1) k_gemm2(
    const float* __restrict__ At, const float* __restrict__ B,
    const float* __restrict__ bias, const float* __restrict__ g,
    const float* __restrict__ be, float* __restrict__ C,
    int M, int Kpad, int Klog, int N, int ldA, int ldB, int ldC)
{
    extern __shared__ float sm[];
    float* As = sm;
    float* Bd = sm + 8192;
    const int t = threadIdx.x;
    const int bm = blockIdx.y * 256, bn = blockIdx.x * 128;
    const int tr = t >> 4, tc = t & 15;

    const float4* At4 = (const float4*)At;
    const float4* B4  = (const float4*)B;
    const int lda4 = ldA >> 2, ldb4 = ldB >> 2;

    float4 ra[4], rb[2];
    unsigned long long acc[8][8];
    #pragma unroll
    for (int i = 0; i < 8; i++)
        #pragma unroll
        for (int j = 0; j < 8; j++) acc[i][j] = 0ull;

    auto LOADG = [&](int k0) {
        #pragma unroll
        for (int i = 0; i < 4; i++) {
            int f = t + 256 * i;
            int kk = f >> 6, m4 = f & 63;
            ra[i] = At4[(size_t)(k0 + kk) * lda4 + (bm >> 2) + m4];
        }
        #pragma unroll
        for (int i = 0; i < 2; i++) {
            int f = t + 256 * i;
            int kk = f >> 5, c4 = f & 31;
            int gk = k0 + kk, gn = bn + c4 * 4;
            if (gk < Klog && gn < N) rb[i] = B4[(size_t)gk * ldb4 + (gn >> 2)];
            else rb[i] = make_float4(0.f, 0.f, 0.f, 0.f);
        }
    };
    auto STORES = [&](int buf) {
        float* Asb = As + buf * 4096;
        float* Bdb = Bd + buf * 4096;
        #pragma unroll
        for (int i = 0; i < 4; i++) {
            int f = t + 256 * i;
            int kk = f >> 6, m4 = f & 63;
            *(float4*)&Asb[kk * 256 + m4 * 4] = ra[i];
        }
        #pragma unroll
        for (int i = 0; i < 2; i++) {
            int f = t + 256 * i;
            int kk = f >> 5, c4 = f & 31;
            int tcb = c4 >> 1, qb = (c4 & 1) * 2;
            *(float4*)&Bdb[((kk * 4 + qb) * 16 + tcb) * 4] =
                make_float4(rb[i].x, rb[i].x, rb[i].y, rb[i].y);
            *(float4*)&Bdb[((kk * 4 + qb + 1) * 16 + tcb) * 4] =
                make_float4(rb[i].z, rb[i].z, rb[i].w, rb[i].w);
        }
    };
    auto COMPUTE = [&](int buf) {
        const float* Asb = As + buf * 4096;
        const float* Bdb = Bd + buf * 4096;
        #pragma unroll
        for (int kk = 0; kk < 16; kk++) {
            unsigned long long a2[8], b2[8];
            #pragma unroll
            for (int r = 0; r < 4; r++) {
                ulonglong2 v = *(const ulonglong2*)&Asb[kk * 256 + tr * 16 + r * 4];
                a2[2 * r] = v.x; a2[2 * r + 1] = v.y;
            }
            #pragma unroll
            for (int q = 0; q < 4; q++) {
                ulonglong2 v = *(const ulonglong2*)&Bdb[(kk * 4 + q) * 64 + tc * 4];
                b2[2 * q] = v.x; b2[2 * q + 1] = v.y;
            }
            #pragma unroll
            for (int ip = 0; ip < 8; ip++)
                #pragma unroll
                for (int j = 0; j < 8; j++)
                    FFMA2(acc[ip][j], a2[ip], b2[j]);
        }
    };

    LOADG(0); STORES(0); __syncthreads();
    int nk = Kpad >> 4;
    int buf = 0;
    for (int it = 1; it < nk; it++) {
        LOADG(it * 16);
        COMPUTE(buf);
        STORES(buf ^ 1);
        __syncthreads();
        buf ^= 1;
    }
    COMPUTE(buf);

    if (TRANSC) {
        #pragma unroll
        for (int j = 0; j < 8; j++) {
            int gn = bn + tc * 8 + j;
            if (gn >= N) continue;
            float bsv = (EPI != 2) ? bias[gn] : 0.f;
            float sv = 0.f, bev = 0.f;
            if (EPI == 1) { sv = __fmul_rn(g[gn], INVF); bev = be[gn]; }
            float v[16];
            #pragma unroll
            for (int ip = 0; ip < 8; ip++) {
                v[2 * ip]     = __uint_as_float((unsigned)(acc[ip][j] & 0xFFFFFFFFull));
                v[2 * ip + 1] = __uint_as_float((unsigned)(acc[ip][j] >> 32));
            }
            #pragma unroll
            for (int r = 0; r < 16; r++) {
                float x = v[r];
                if (EPI != 2) x = __fadd_rn(x, bsv);
                if (EPI == 1) { x = __fadd_rn(__fmul_rn(x, sv), bev); x = fmaxf(x, 0.f); }
                v[r] = x;
            }
            int gmb = bm + tr * 16;
            if (gmb + 16 <= M) {
                #pragma unroll
                for (int r4 = 0; r4 < 4; r4++)
                    *(float4*)&C[(size_t)gn * ldC + gmb + r4 * 4] =
                        make_float4(v[r4 * 4], v[r4 * 4 + 1], v[r4 * 4 + 2], v[r4 * 4 + 3]);
            } else {
                for (int r = 0; r < 16; r++)
                    if (gmb + r < M) C[(size_t)gn * ldC + gmb + r] = v[r];
            }
        }
    } else {
        #pragma unroll
        for (int ip = 0; ip < 8; ip++) {
            #pragma unroll
            for (int h = 0; h < 2; h++) {
                int gm = bm + tr * 16 + 2 * ip + h;
                if (gm >= M) continue;
                float v[8];
                #pragma unroll
                for (int j = 0; j < 8; j++) {
                    unsigned long long a = acc[ip][j];
                    float x = h ? __uint_as_float((unsigned)(a >> 32))
                                : __uint_as_float((unsigned)(a & 0xFFFFFFFFull));
                    int gn = bn + tc * 8 + j;
                    if (EPI != 2) x = __fadd_rn(x, bias[gn]);
                    if (EPI == 1) {
                        x = __fadd_rn(__fmul_rn(x, __fmul_rn(g[gn], INVF)), be[gn]);
                        x = fmaxf(x, 0.f);
                    }
                    v[j] = x;
                }
                int gn0 = bn + tc * 8;
                if (gn0 + 8 <= N) {
                    *(float4*)&C[(size_t)gm * ldC + gn0]     = make_float4(v[0], v[1], v[2], v[3]);
                    *(float4*)&C[(size_t)gm * ldC + gn0 + 4] = make_float4(v[4], v[5], v[6], v[7]);
                } else {
                    for (int j = 0; j < 8; j++)
                        if (gn0 + j < N) C[(size_t)gm * ldC + gn0 + j] = v[j];
                }
            }
        }
    }
}

// ---------------- upsample + pos + bn epilogue -> x1T ----------------
__device__ __forceinline__ float4 f4blend(float4 A, float4 B, float wa, float wb) {
    float4 r;
    r.x = __fadd_rn(__fmul_rn(A.x, wa), __fmul_rn(B.x, wb));
    r.y = __fadd_rn(__fmul_rn(A.y, wa), __fmul_rn(B.y, wb));
    r.z = __fadd_rn(__fmul_rn(A.z, wa), __fmul_rn(B.z, wb));
    r.w = __fadd_rn(__fmul_rn(A.w, wa), __fmul_rn(B.w, wb));
    return r;
}
__device__ __forceinline__ float4 f4add(float4 A, float4 B) {
    float4 r;
    r.x = __fadd_rn(A.x, B.x); r.y = __fadd_rn(A.y, B.y);
    r.z = __fadd_rn(A.z, B.z); r.w = __fadd_rn(A.w, B.w);
    return r;
}

__global__ void __launch_bounds__(256) k_up(
    const float* __restrict__ b0a, const float* __restrict__ g0a,
    const float* __restrict__ be0a)
{
    int t = threadIdx.x;
    int nt = t & 63, jt = t >> 6;
    int n0 = blockIdx.y * 256 + nt * 4;
    int j0 = blockIdx.x * 64 + jt * 16;
    int b = n0 >> 16, y = (n0 >> 8) & 255;
    int x0 = n0 & 255;
    int k = x0 >> 2;

    float cyf = ((float)y + 0.5f) * 0.25f - 0.5f;
    float fy0f = floorf(cyf);
    float fy = cyf - fy0f;
    int yy0 = (int)fy0f;
    int iy0 = min(max(yy0, 0), 63), iy1 = min(max(yy0 + 1, 0), 63);
    bool yeq = (iy0 == iy1);
    float wy0 = 1.f - fy;

    int ca = max(k - 1, 0), cb = k, cc = min(k + 1, 63);
    const float* E0 = g_embw + ((size_t)(b * 4096 + iy0 * 64)) * NF4;
    const float* E1 = g_embw + ((size_t)(b * 4096 + iy1 * 64)) * NF4;

    #pragma unroll
    for (int jg = 0; jg < 4; jg++) {
        int j = j0 + jg * 4;
        float4 a0 = *(const float4*)(E0 + (size_t)ca * NF4 + j);
        float4 b0 = *(const float4*)(E0 + (size_t)cb * NF4 + j);
        float4 c0 = *(const float4*)(E0 + (size_t)cc * NF4 + j);
        float4 Ta, Tb, Tc;
        if (yeq) { Ta = a0; Tb = b0; Tc = c0; }
        else {
            float4 a1 = *(const float4*)(E1 + (size_t)ca * NF4 + j);
            float4 b1 = *(const float4*)(E1 + (size_t)cb * NF4 + j);
            float4 c1 = *(const float4*)(E1 + (size_t)cc * NF4 + j);
            Ta = f4blend(a0, a1, wy0, fy);
            Tb = f4blend(b0, b1, wy0, fy);
            Tc = f4blend(c0, c1, wy0, fy);
        }
        float4 py  = *(const float4*)&g_posy[y * NF4 + j];
        float4 bsv = *(const float4*)&b0a[j];
        float4 gv  = *(const float4*)&g0a[j];
        float4 bev = *(const float4*)&be0a[j];
        float4 sc;
        sc.x = __fmul_rn(gv.x, INVF); sc.y = __fmul_rn(gv.y, INVF);
        sc.z = __fmul_rn(gv.z, INVF); sc.w = __fmul_rn(gv.w, INVF);

        float res[4][4];
        #pragma unroll
        for (int xi = 0; xi < 4; xi++) {
            float4 px = *(const float4*)&g_posx[(x0 + xi) * NF4 + j];
            float4 TL, TR; bool cp; float fx;
            if (xi < 2) { TL = Ta; TR = Tb; cp = (k == 0);  fx = (xi == 0) ? 0.625f : 0.875f; }
            else        { TL = Tb; TR = Tc; cp = (k == 63); fx = (xi == 2) ? 0.125f : 0.375f; }
            float wx = 1.f - fx;
            float4 v = cp ? TL : f4blend(TL, TR, wx, fx);
            v = f4add(v, py); v = f4add(v, px); v = f4add(v, bsv);
            v.x = fmaxf(__fadd_rn(__fmul_rn(v.x, sc.x), bev.x), 0.f);
            v.y = fmaxf(__fadd_rn(__fmul_rn(v.y, sc.y), bev.y), 0.f);
            v.z = fmaxf(__fadd_rn(__fmul_rn(v.z, sc.z), bev.z), 0.f);
            v.w = fmaxf(__fadd_rn(__fmul_rn(v.w, sc.w), bev.w), 0.f);
            res[xi][0] = v.x; res[xi][1] = v.y; res[xi][2] = v.z; res[xi][3] = v.w;
        }
        #pragma unroll
        for (int d = 0; d < 4; d++)
            *(float4*)&g_x1T[(size_t)(j + d) * NTOT + n0] =
                make_float4(res[0][d], res[1][d], res[2][d], res[3][d]);
    }
}

// ---------------- head col 128 ----------------
__global__ void k_hcol(const float* __restrict__ b2) {
    int n = blockIdx.x * 256 + threadIdx.x;
    float acc = 0.f;
    #pragma unroll 8
    for (int k = 0; k < 256; k++)
        acc = fmaf(g_x2T[(size_t)k * NTOT + n], g_w2c[k], acc);
    g_hcol[n] = __fadd_rn(acc, b2[128]);
}

// ---------------- head post: segc / var (bit-frozen) ----------------
__global__ void k_post(const void* __restrict__ dm1, const void* __restrict__ dm2) {
    int w = (int)((blockIdx.x * (size_t)blockDim.x + threadIdx.x) >> 5);
    int lane = threadIdx.x & 31;
    if (w >= NTOT) return;
    int mode = g_maskmode;
    float acc = 0.f;
    for (int c = lane; c < NHEAD; c += 32) {
        float h = (c < 128) ? g_head[(size_t)w * 128 + c] : g_hcol[w];
        size_t mi = (size_t)w * NHEAD + c;
        float m1 = maskval(dm1, mi, mode);
        float m2 = maskval(dm2, mi, mode);
        if (c == 0) g_segc[w] = __fmul_rn(__fmul_rn(h, m2), 2.0f);
        float o2 = __fmul_rn(__fmul_rn(h, m2), 2.0f);
        float o1 = __fmul_rn(__fmul_rn(h, m1), 2.0f);
        float d  = __fsub_rn(o1, o2);
        acc = __fadd_rn(acc, __fmul_rn(0.5f, __fmul_rn(d, d)));
    }
    #pragma unroll
    for (int o = 16; o; o >>= 1) acc = __fadd_rn(acc, __shfl_xor_sync(~0u, acc, o));
    if (!lane) g_var[w] = __fdiv_rn(acc, 129.0f);
}

// ---------------- top-k ----------------
__global__ void k_hist(int phase) {
    int i = blockIdx.x * blockDim.x + threadIdx.x;
    if (i >= NTOT) return;
    unsigned key = __float_as_uint(g_var[i]);
    if (phase == 0) atomicAdd(&g_hist[0][key >> 21], 1u);
    else if (phase == 1) {
        if ((key >> 21) == g_bin[0]) atomicAdd(&g_hist[1][(key >> 10) & 0x7FFu], 1u);
    } else {
        if ((key >> 10) == ((g_bin[0] << 11) | g_bin[1]))
            atomicAdd(&g_hist[2][key & 0x3FFu], 1u);
    }
}

// Parallel scan: exact same selection semantics as the serial top-down walk
// (b=0 fallback when no bin b>0 crosses).
__global__ void k_scan2(int phase) {
    __shared__ unsigned csum[256];
    __shared__ unsigned suf[256];
    int t = threadIdx.x;
    unsigned need = (phase == 0) ? (unsigned)KSEL : g_need_s;
    const unsigned* H = g_hist[phase];
    unsigned h[8]; unsigned s = 0;
    #pragma unroll
    for (int i = 0; i < 8; i++) { h[i] = H[t * 8 + i]; s += h[i]; }
    csum[t] = s;
    __syncthreads();
    if (t == 0) {
        unsigned a = 0;
        for (int u = 255; u >= 0; u--) { suf[u] = a; a += csum[u]; }
    }
    __syncthreads();
    unsigned se = suf[t];
    if (se < need && se + csum[t] >= need) {
        unsigned acc = se;
        int b = -1;
        int lo = (t == 0) ? 1 : 0;
        for (int i = 7; i >= lo; i--) {
            unsigned hh = h[i];
            if (acc + hh >= need) { b = t * 8 + i; break; }
            acc += hh;
        }
        if (b < 0) b = 0;
        g_bin[phase] = (unsigned)b;
        g_need_s = need - acc;
        if (phase == 2) {
            g_thresh_bits = (g_bin[0] << 21) | (g_bin[1] << 10) | (unsigned)b;
            g_need_eq = (int)(need - acc);
        }
    }
}

__global__ void k_compact(float* __restrict__ out) {
    int i = blockIdx.x * blockDim.x + threadIdx.x;
    if (i >= NTOT) return;
    float vv = g_segc[i];
    out[i] = vv;
    out[NTOT + i] = vv;
    unsigned key = __float_as_uint(g_var[i]);
    unsigned T = g_thresh_bits;
    if (key > T) {
        unsigned s = atomicAdd(&g_cnt_gt, 1u);
        g_sel[s] = i;
    } else if (key == T) {
        unsigned e = atomicAdd(&g_cnt_eq, 1u);
        if (e < 8192u) g_eq[e] = i;
    }
}

__global__ void k_eqsel() {
    int c = (int)g_cnt_eq; if (c > 8192) c = 8192;
    int need = g_need_eq;
    int G = KSEL - need;
    for (int i = threadIdx.x; i < c; i += blockDim.x) {
        int v = g_eq[i];
        int rank = 0;
        for (int j = 0; j < c; j++) rank += (g_eq[j] < v) ? 1 : 0;
        if (rank < need) g_sel[G + rank] = v;
    }
}

// ---------------- lazy fine-input build: fineinT[c][j] ----------------
__global__ void k_gatherfine(const float* __restrict__ emb, const float* __restrict__ pe,
                             const void* __restrict__ dm2) {
    size_t idx = (size_t)blockIdx.x * 256 + threadIdx.x;
    if (idx >= (size_t)KPF * MT) return;
    int c = (int)(idx / MT);
    int j = (int)(idx - (size_t)c * MT);
    float v = 0.f;
    if (j < KSEL && c < FINEIN) {
        int s = g_sel[j];
        int b = s >> 16, y = (s >> 8) & 255, x = s & 255;
        if (c < CEMB + CPE) {
            const float* plane = (c < CEMB)
                ? emb + ((size_t)(b * CEMB + c)) * 4096
                : pe  + ((size_t)(b * CPE + (c - CEMB))) * 4096;
            float cyf = ((float)y + 0.5f) * 0.25f - 0.5f;
            float cxf = ((float)x + 0.5f) * 0.25f - 0.5f;
            float fy0 = floorf(cyf), fx0 = floorf(cxf);
            float fy = cyf - fy0, fx = cxf - fx0;
            int y0 = (int)fy0, x0 = (int)fx0;
            int iy0 = min(max(y0, 0), 63), iy1 = min(max(y0 + 1, 0), 63);
            int ix0 = min(max(x0, 0), 63), ix1 = min(max(x0 + 1, 0), 63);
            float v00 = plane[iy0 * 64 + ix0], v01 = plane[iy0 * 64 + ix1];
            float v10 = plane[iy1 * 64 + ix0], v11 = plane[iy1 * 64 + ix1];
            float wy0 = 1.f - fy, wx0 = 1.f - fx;
            float t0, t1;
            if (iy0 == iy1) { t0 = v00; t1 = v01; }
            else {
                t0 = __fadd_rn(__fmul_rn(v00, wy0), __fmul_rn(v10, fy));
                t1 = __fadd_rn(__fmul_rn(v01, wy0), __fmul_rn(v11, fy));
            }
            v = (ix0 == ix1) ? t0
                : __fadd_rn(__fmul_rn(t0, wx0), __fmul_rn(t1, fx));
        } else if (c < INDIM) {
            int p = c - (CEMB + CPE);
            if      (p < 10) v = g_tab[y][p];
            else if (p < 20) v = g_tab[x][p - 10];
            else if (p < 30) v = g_tab[y][p - 10];
            else if (p < 40) v = g_tab[x][p - 20];
            else v = (p == 40) ? g_coord[y] : g_coord[x];
        } else {
            int col = c - 201;   // 1..128
            float h = (col < 128) ? g_head[(size_t)s * 128 + col] : g_hcol[s];
            float m2 = maskval(dm2, (size_t)s * NHEAD + col, g_maskmode);
            v = __fmul_rn(__fmul_rn(h, m2), 2.0f);
        }
    }
    g_fineinT[idx] = v;
}

// ---------------- final fine dot + scatter ----------------
__global__ void k_zdot(const float* __restrict__ w3b, const float* __restrict__ b3b,
                       float* __restrict__ out) {
    int j = (int)((blockIdx.x * (size_t)blockDim.x + threadIdx.x) >> 5);
    int lane = threadIdx.x & 31;
    if (j >= KSEL) return;
    float v0  = g_zT[(size_t)lane * MT + j];
    float v32 = g_zT[(size_t)(32 + lane) * MT + j];
    float acc = __fadd_rn(__fmul_rn(v0, w3b[lane]), __fmul_rn(v32, w3b[32 + lane]));
    #pragma unroll
    for (int o = 16; o; o >>= 1) acc = __fadd_rn(acc, __shfl_xor_sync(~0u, acc, o));
    if (!lane) out[NTOT + g_sel[j]] = __fadd_rn(acc, b3b[0]);
}

// ---------------- launch ----------------
extern "C" void kernel_launch(void* const* d_in, const int* in_sizes, int n_in,
                              void* d_out, int out_size) {
    const float* emb = (const float*)d_in[0];
    const float* pe  = (const float*)d_in[1];
    const void*  dm1 = d_in[2];
    const void*  dm2 = d_in[3];
    const float* w0a = (const float*)d_in[4];
    const float* b0a = (const float*)d_in[5];
    const float* g0a = (const float*)d_in[6];
    const float* be0a= (const float*)d_in[7];
    const float* w0b = (const float*)d_in[8];
    const float* b0b = (const float*)d_in[9];
    const float* g0b = (const float*)d_in[10];
    const float* be0b= (const float*)d_in[11];
    const float* w2  = (const float*)d_in[12];
    const float* b2  = (const float*)d_in[13];
    const float* w1a = (const float*)d_in[14];
    const float* b1a = (const float*)d_in[15];
    const float* g1a = (const float*)d_in[16];
    const float* be1a= (const float*)d_in[17];
    const float* w1b = (const float*)d_in[18];
    const float* b1b = (const float*)d_in[19];
    const float* g1b = (const float*)d_in[20];
    const float* be1b= (const float*)d_in[21];
    const float* w3a = (const float*)d_in[22];
    const float* b3a = (const float*)d_in[23];
    const float* g3a = (const float*)d_in[24];
    const float* be3a= (const float*)d_in[25];
    const float* w3b = (const float*)d_in[26];
    const float* b3b = (const float*)d_in[27];
    float* out = (float*)d_out;

    const int SMEMSZ = 65536;
    cudaFuncSetAttribute(k_gemm2<1,1>, cudaFuncAttributeMaxDynamicSharedMemorySize, SMEMSZ);
    cudaFuncSetAttribute(k_gemm2<0,0>, cudaFuncAttributeMaxDynamicSharedMemorySize, SMEMSZ);
    cudaFuncSetAttribute(k_gemm2<2,0>, cudaFuncAttributeMaxDynamicSharedMemorySize, SMEMSZ);

    float *p_lowT, *p_embw, *p_x1T, *p_x2T, *p_head, *p_fin, *p_y1T, *p_y2T, *p_zT, *p_w2p;
    cudaGetSymbolAddress((void**)&p_lowT, g_lowT);
    cudaGetSymbolAddress((void**)&p_embw, g_embw);
    cudaGetSymbolAddress((void**)&p_x1T,  g_x1T);
    cudaGetSymbolAddress((void**)&p_x2T,  g_x2T);
    cudaGetSymbolAddress((void**)&p_head, g_head);
    cudaGetSymbolAddress((void**)&p_fin,  g_fineinT);
    cudaGetSymbolAddress((void**)&p_y1T,  g_y1T);
    cudaGetSymbolAddress((void**)&p_y2T,  g_y2T);
    cudaGetSymbolAddress((void**)&p_zT,   g_zT);
    cudaGetSymbolAddress((void**)&p_w2p,  g_w2p);

    k_prelude<<<132, 256>>>((const unsigned*)dm1, w2);
    k_lowT<<<(160 * NLOW) / 256, 256>>>(emb, pe);
    // low-res GEMM: embw[8192][512] = lowfeat @ w0a[0:160] (raw, no bias)
    k_gemm2<2,0><<<dim3(NF4/128, NLOW/256), 256, SMEMSZ>>>(p_lowT, w0a, b0a, b0a, b0a, p_embw, NLOW, 160, 160, NF4, NLOW, NF4, NF4);
    k_posw<<<(256 * NF4) / 256, 256>>>(w0a);
    // upsample + pos + bias + bn + relu -> x1T
    k_up<<<dim3(8, 512), 256>>>(b0a, g0a, be0a);

    // coarse MLP layers 2,3
    k_gemm2<1,1><<<dim3(NF2/128, NTOT/256), 256, SMEMSZ>>>(p_x1T, w0b, b0b, g0b, be0b, p_x2T, NTOT, NF4, NF4, NF2, NTOT, NF2, NTOT);
    k_gemm2<0,0><<<dim3(1, NTOT/256), 256, SMEMSZ>>>(p_x2T, p_w2p, b2, b2, b2, p_head, NTOT, NF2, NF2, 128, NTOT, 128, 128);
    k_hcol<<<NTOT/256, 256>>>(b2);

    k_post<<<NTOT/8, 256>>>(dm1, dm2);

    // top-k
    int hb = (NTOT + 255) / 256;
    k_hist<<<hb, 256>>>(0);
    k_scan2<<<1, 256>>>(0);
    k_hist<<<hb, 256>>>(1);
    k_scan2<<<1, 256>>>(1);
    k_hist<<<hb, 256>>>(2);
    k_scan2<<<1, 256>>>(2);
    k_compact<<<hb, 256>>>(out);
    k_eqsel<<<1, 256>>>();

    {
        size_t tot = (size_t)KPF * MT;
        k_gatherfine<<<(unsigned)((tot + 255) / 256), 256>>>(emb, pe, dm2);
    }

    // fine MLP
    int gy = (KSEL + 255) / 256;
    k_gemm2<1,1><<<dim3(1, gy), 256, SMEMSZ>>>(p_fin, w1a, b1a, g1a, be1a, p_y1T, KSEL, KPF, FINEIN, NFEAT, MT, NFEAT, MT);
    k_gemm2<1,1><<<dim3(1, gy), 256, SMEMSZ>>>(p_y1T, w1b, b1b, g1b, be1b, p_y2T, KSEL, NFEAT, NFEAT, NFEAT, MT, NFEAT, MT);
    k_gemm2<1,1><<<dim3(1, gy), 256, SMEMSZ>>>(p_y2T, w3a, b3a, g3a, be3a, p_zT, KSEL, NFEAT, NFEAT, 64, MT, 64, MT);

    k_zdot<<<(KSEL * 32 + 255) / 256, 256>>>(w3b, b3b, out);
}